// round 1
// baseline (speedup 1.0000x reference)
#include <cuda_runtime.h>
#include <cstdint>

#define BATCH 32
#define NN    768
#define DD    768

// Scratch: e1 = X @ W_l1  (75.5 MB), rinv (96 KB)
__device__ float g_e1[(size_t)BATCH * NN * DD];
__device__ float g_rinv[BATCH * NN];

// ---------------------------------------------------------------------------
// rowsum^{-1} of adj: one warp per row
// ---------------------------------------------------------------------------
__global__ void rowinv_kernel(const float* __restrict__ adj) {
    int row = blockIdx.x * blockDim.y + threadIdx.y;   // 0 .. B*N-1
    if (row >= BATCH * NN) return;
    const float* p = adj + (size_t)row * NN;
    float s = 0.f;
    for (int i = threadIdx.x; i < NN; i += 32) s += p[i];
#pragma unroll
    for (int o = 16; o > 0; o >>= 1) s += __shfl_down_sync(0xffffffffu, s, o);
    if (threadIdx.x == 0) g_rinv[row] = (s == 0.f) ? 0.f : (1.f / s);
}

// ---------------------------------------------------------------------------
// GEMM1: C = A(M x K) @ W(K x 768), M = B*N, K = D.
//   gridDim.z == 0 : W = W_l1 -> g_e1
//   gridDim.z == 1 : W = W_l  -> d_out  (holds X1 temporarily)
// 128x128 block tile, BK=8, 256 threads, 8x8 per-thread microtile.
// All dims are multiples of 128 so no bounds checks.
// ---------------------------------------------------------------------------
__global__ __launch_bounds__(256, 2)
void gemm_xw_kernel(const float* __restrict__ X,
                    const float* __restrict__ W_l,
                    const float* __restrict__ W_l1,
                    float* __restrict__ out)
{
    __shared__ float As[8][128];
    __shared__ float Bs[8][128];

    const float* W = (blockIdx.z == 0) ? W_l1 : W_l;
    float* C = (blockIdx.z == 0) ? g_e1 : out;

    const int tid  = threadIdx.x;
    const int aRow = tid >> 1;            // 0..127
    const int aCol = (tid & 1) * 4;       // 0 or 4
    const int bRow = tid >> 5;            // 0..7
    const int bCol = (tid & 31) * 4;      // 0..124
    const int tx   = (tid & 15) * 8;      // col base in tile
    const int ty   = (tid >> 4) * 8;      // row base in tile

    const size_t mBase = (size_t)blockIdx.y * 128;
    const int    nBase = blockIdx.x * 128;

    const float* Aptr = X + (mBase + aRow) * DD + aCol;
    const float* Bptr = W + (size_t)bRow * DD + nBase + bCol;

    float acc[8][8];
#pragma unroll
    for (int i = 0; i < 8; i++)
#pragma unroll
        for (int j = 0; j < 8; j++) acc[i][j] = 0.f;

    for (int kt = 0; kt < DD; kt += 8) {
        float4 av = *(const float4*)(Aptr + kt);
        As[aCol + 0][aRow] = av.x;
        As[aCol + 1][aRow] = av.y;
        As[aCol + 2][aRow] = av.z;
        As[aCol + 3][aRow] = av.w;
        float4 bv = *(const float4*)(Bptr + (size_t)kt * DD);
        *(float4*)&Bs[bRow][bCol] = bv;
        __syncthreads();

#pragma unroll
        for (int k = 0; k < 8; k++) {
            float ar[8], br[8];
            *(float4*)&ar[0] = *(const float4*)&As[k][ty];
            *(float4*)&ar[4] = *(const float4*)&As[k][ty + 4];
            *(float4*)&br[0] = *(const float4*)&Bs[k][tx];
            *(float4*)&br[4] = *(const float4*)&Bs[k][tx + 4];
#pragma unroll
            for (int i = 0; i < 8; i++)
#pragma unroll
                for (int j = 0; j < 8; j++)
                    acc[i][j] = fmaf(ar[i], br[j], acc[i][j]);
        }
        __syncthreads();
    }

#pragma unroll
    for (int i = 0; i < 8; i++) {
        float* crow = C + (mBase + ty + i) * DD + nBase + tx;
        float4 v0 = make_float4(acc[i][0], acc[i][1], acc[i][2], acc[i][3]);
        float4 v1 = make_float4(acc[i][4], acc[i][5], acc[i][6], acc[i][7]);
        *(float4*)(crow)     = v0;
        *(float4*)(crow + 4) = v1;
    }
}

// ---------------------------------------------------------------------------
// GEMM2 + epilogue: per batch b
//   acc = adj_b (N x N) @ e1_b (N x D)
//   out = leaky_relu( rinv[row] * acc + X1 )   where X1 currently lives in d_out
// gridDim = (6, 6, 32)
// ---------------------------------------------------------------------------
__global__ __launch_bounds__(256, 2)
void gemm_agg_kernel(const float* __restrict__ adj,
                     float* __restrict__ out)
{
    __shared__ float As[8][128];
    __shared__ float Bs[8][128];

    const int b = blockIdx.z;
    const float* A = adj  + (size_t)b * NN * NN;
    const float* B = g_e1 + (size_t)b * NN * DD;

    const int tid  = threadIdx.x;
    const int aRow = tid >> 1;
    const int aCol = (tid & 1) * 4;
    const int bRow = tid >> 5;
    const int bCol = (tid & 31) * 4;
    const int tx   = (tid & 15) * 8;
    const int ty   = (tid >> 4) * 8;

    const int mBase = blockIdx.y * 128;
    const int nBase = blockIdx.x * 128;

    const float* Aptr = A + (size_t)(mBase + aRow) * NN + aCol;
    const float* Bptr = B + (size_t)bRow * DD + nBase + bCol;

    float acc[8][8];
#pragma unroll
    for (int i = 0; i < 8; i++)
#pragma unroll
        for (int j = 0; j < 8; j++) acc[i][j] = 0.f;

    for (int kt = 0; kt < NN; kt += 8) {
        float4 av = *(const float4*)(Aptr + kt);
        As[aCol + 0][aRow] = av.x;
        As[aCol + 1][aRow] = av.y;
        As[aCol + 2][aRow] = av.z;
        As[aCol + 3][aRow] = av.w;
        float4 bv = *(const float4*)(Bptr + (size_t)kt * DD);
        *(float4*)&Bs[bRow][bCol] = bv;
        __syncthreads();

#pragma unroll
        for (int k = 0; k < 8; k++) {
            float ar[8], br[8];
            *(float4*)&ar[0] = *(const float4*)&As[k][ty];
            *(float4*)&ar[4] = *(const float4*)&As[k][ty + 4];
            *(float4*)&br[0] = *(const float4*)&Bs[k][tx];
            *(float4*)&br[4] = *(const float4*)&Bs[k][tx + 4];
#pragma unroll
            for (int i = 0; i < 8; i++)
#pragma unroll
                for (int j = 0; j < 8; j++)
                    acc[i][j] = fmaf(ar[i], br[j], acc[i][j]);
        }
        __syncthreads();
    }

    // Epilogue: scale by rinv, add X1 (in out), leaky_relu, store.
#pragma unroll
    for (int i = 0; i < 8; i++) {
        int row = mBase + ty + i;
        float rv = g_rinv[b * NN + row];
        float* crow = out + ((size_t)b * NN + row) * DD + nBase + tx;
        float4 x0 = *(const float4*)(crow);
        float4 x1 = *(const float4*)(crow + 4);
        float h[8];
        h[0] = fmaf(rv, acc[i][0], x0.x);
        h[1] = fmaf(rv, acc[i][1], x0.y);
        h[2] = fmaf(rv, acc[i][2], x0.z);
        h[3] = fmaf(rv, acc[i][3], x0.w);
        h[4] = fmaf(rv, acc[i][4], x1.x);
        h[5] = fmaf(rv, acc[i][5], x1.y);
        h[6] = fmaf(rv, acc[i][6], x1.z);
        h[7] = fmaf(rv, acc[i][7], x1.w);
#pragma unroll
        for (int j = 0; j < 8; j++)
            h[j] = (h[j] > 0.f) ? h[j] : 0.01f * h[j];
        *(float4*)(crow)     = make_float4(h[0], h[1], h[2], h[3]);
        *(float4*)(crow + 4) = make_float4(h[4], h[5], h[6], h[7]);
    }
}

// ---------------------------------------------------------------------------
extern "C" void kernel_launch(void* const* d_in, const int* in_sizes, int n_in,
                              void* d_out, int out_size)
{
    const float* X    = (const float*)d_in[0];   // [B, N, D]
    const float* adj  = (const float*)d_in[1];   // [B, N, N]
    const float* W_l  = (const float*)d_in[2];   // [D, D]
    const float* W_l1 = (const float*)d_in[3];   // [D, D]
    float* out = (float*)d_out;                  // [B, N, D]

    // 1) rinv
    {
        dim3 blk(32, 8);
        dim3 grd((BATCH * NN + 7) / 8);
        rowinv_kernel<<<grd, blk>>>(adj);
    }
    // 2) e1 = X@W_l1 (z=0), X1 = X@W_l -> out (z=1)
    {
        dim3 blk(256);
        dim3 grd(DD / 128, (BATCH * NN) / 128, 2);
        gemm_xw_kernel<<<grd, blk>>>(X, W_l, W_l1, out);
    }
    // 3) out = lrelu(rinv * (adj @ e1) + out)
    {
        dim3 blk(256);
        dim3 grd(DD / 128, NN / 128, BATCH);
        gemm_agg_kernel<<<grd, blk>>>(adj, out);
    }
}

// round 3
// speedup vs baseline: 2.1246x; 2.1246x over previous
#include <cuda_runtime.h>
#include <cuda_bf16.h>
#include <cstdint>

#define BATCH 32
#define NDIM  768
#define MTOT  (BATCH * NDIM)     // 24576
#define BK    32
#define NKT   (NDIM / BK)        // 24

// ---------------------------------------------------------------------------
// Scratch
// ---------------------------------------------------------------------------
__device__ float g_e1[(size_t)MTOT * NDIM];   // X @ W_l1, fp32
__device__ float g_rinv[MTOT];

// ---------------------------------------------------------------------------
// smem geometry (bf16 elements). A tile 128 x 32 (pad->40), B tile 32 x 128 (pad->136)
// ---------------------------------------------------------------------------
#define APAD 40
#define BPAD 136
#define SZ_A (128 * APAD)                    // 5120
#define SZ_B (BK * BPAD)                     // 4352
#define STAGE_ELEMS (2 * SZ_A + 2 * SZ_B)    // 18944 elems = 37888 B
#define SMEM_BYTES (2 * STAGE_ELEMS * 2)     // 75776 B

// elem offsets within a stage
#define OFF_AHI 0
#define OFF_ALO SZ_A
#define OFF_BHI (2 * SZ_A)
#define OFF_BLO (2 * SZ_A + SZ_B)

// ---------------------------------------------------------------------------
// PTX helpers (all plain sm_80+ instructions; no 'a'-suffix features)
// ---------------------------------------------------------------------------
__device__ __forceinline__ uint32_t smem_u32(const void* p) {
    uint32_t a;
    asm("{ .reg .u64 t; cvta.to.shared.u64 t, %1; cvt.u32.u64 %0, t; }" : "=r"(a) : "l"(p));
    return a;
}
__device__ __forceinline__ void ldsm4(uint32_t* r, uint32_t addr) {
    asm volatile("ldmatrix.sync.aligned.m8n8.x4.shared.b16 {%0,%1,%2,%3}, [%4];"
                 : "=r"(r[0]), "=r"(r[1]), "=r"(r[2]), "=r"(r[3]) : "r"(addr));
}
__device__ __forceinline__ void ldsm4t(uint32_t* r, uint32_t addr) {
    asm volatile("ldmatrix.sync.aligned.m8n8.x4.trans.shared.b16 {%0,%1,%2,%3}, [%4];"
                 : "=r"(r[0]), "=r"(r[1]), "=r"(r[2]), "=r"(r[3]) : "r"(addr));
}
__device__ __forceinline__ void hmma(float* d, const uint32_t* a, const uint32_t* b) {
    asm volatile("mma.sync.aligned.m16n8k16.row.col.f32.bf16.bf16.f32 "
                 "{%0,%1,%2,%3}, {%4,%5,%6,%7}, {%8,%9}, {%0,%1,%2,%3};"
                 : "+f"(d[0]), "+f"(d[1]), "+f"(d[2]), "+f"(d[3])
                 : "r"(a[0]), "r"(a[1]), "r"(a[2]), "r"(a[3]), "r"(b[0]), "r"(b[1]));
}

__device__ __forceinline__ void split4(float4 v, uint2& hi, uint2& lo) {
    __nv_bfloat16 h0 = __float2bfloat16(v.x);
    __nv_bfloat16 h1 = __float2bfloat16(v.y);
    __nv_bfloat16 h2 = __float2bfloat16(v.z);
    __nv_bfloat16 h3 = __float2bfloat16(v.w);
    __nv_bfloat16 l0 = __float2bfloat16(v.x - __bfloat162float(h0));
    __nv_bfloat16 l1 = __float2bfloat16(v.y - __bfloat162float(h1));
    __nv_bfloat16 l2 = __float2bfloat16(v.z - __bfloat162float(h2));
    __nv_bfloat16 l3 = __float2bfloat16(v.w - __bfloat162float(h3));
    hi.x = ((uint32_t)__bfloat16_as_ushort(h1) << 16) | __bfloat16_as_ushort(h0);
    hi.y = ((uint32_t)__bfloat16_as_ushort(h3) << 16) | __bfloat16_as_ushort(h2);
    lo.x = ((uint32_t)__bfloat16_as_ushort(l1) << 16) | __bfloat16_as_ushort(l0);
    lo.y = ((uint32_t)__bfloat16_as_ushort(l3) << 16) | __bfloat16_as_ushort(l2);
}

// ---------------------------------------------------------------------------
// rowsum^{-1} of adj: one warp per row
// ---------------------------------------------------------------------------
__global__ void rowinv_kernel(const float* __restrict__ adj) {
    int row = blockIdx.x * blockDim.y + threadIdx.y;
    if (row >= MTOT) return;
    const float* p = adj + (size_t)row * NDIM;
    float s = 0.f;
    for (int i = threadIdx.x; i < NDIM; i += 32) s += p[i];
#pragma unroll
    for (int o = 16; o > 0; o >>= 1) s += __shfl_down_sync(0xffffffffu, s, o);
    if (threadIdx.x == 0) g_rinv[row] = (s == 0.f) ? 0.f : (1.f / s);
}

// ---------------------------------------------------------------------------
// GEMM core: C[mb:mb+128, nb:nb+128] (+)= A[mb:,:768] @ B[:768, nb:]
// A, B fp32 row-major with ld 768. 3-term bf16 split done in-kernel.
// SCALE_A: multiply A rows by rinv[row] before split.
// FUSED:   C = leaky_relu(acc + C_old) (read-modify-write), else C = acc.
// ---------------------------------------------------------------------------
template<bool SCALE_A, bool FUSED>
__device__ __forceinline__ void gemm_body(
    const float* __restrict__ Ag, const float* __restrict__ Bg,
    const float* __restrict__ rinv, float* __restrict__ Cg,
    int mb, int nb)
{
    extern __shared__ __nv_bfloat16 sm[];
    const uint32_t smb = smem_u32(sm);

    const int tid  = threadIdx.x;
    const int lane = tid & 31;
    const int wid  = tid >> 5;
    const int wm   = wid >> 1;        // 0..3 -> 32-row band
    const int wn   = wid & 1;         // 0..1 -> 64-col band

    // prefetch mapping (constant over kt)
    const int acol = (tid & 7) * 4;        // k offset within chunk
    const int bcol = (tid & 31) * 4;       // n offset within tile
    int arow[4], brow[4];
    float rv[4];
#pragma unroll
    for (int i = 0; i < 4; i++) {
        arow[i] = 32 * i + (tid >> 3);
        brow[i] = 8 * i + wid;
        if (SCALE_A) rv[i] = rinv[arow[i]];   // rinv already offset to mb by caller
    }

    float4 av[4], bv[4];
    float acc[2][8][4];
#pragma unroll
    for (int i = 0; i < 2; i++)
#pragma unroll
        for (int j = 0; j < 8; j++)
#pragma unroll
            for (int q = 0; q < 4; q++) acc[i][j][q] = 0.f;

    // ---- prefetch chunk 0
#pragma unroll
    for (int i = 0; i < 4; i++) {
        av[i] = *(const float4*)(Ag + (size_t)(mb + arow[i]) * NDIM + acol);
        bv[i] = *(const float4*)(Bg + (size_t)brow[i] * NDIM + nb + bcol);
    }
    // ---- store chunk 0 into stage 0
#pragma unroll
    for (int i = 0; i < 4; i++) {
        float4 va = av[i];
        if (SCALE_A) { va.x *= rv[i]; va.y *= rv[i]; va.z *= rv[i]; va.w *= rv[i]; }
        uint2 hi, lo;
        split4(va, hi, lo);
        int ao = arow[i] * APAD + acol;
        *(uint2*)(sm + OFF_AHI + ao) = hi;
        *(uint2*)(sm + OFF_ALO + ao) = lo;
        split4(bv[i], hi, lo);
        int bo = brow[i] * BPAD + bcol;
        *(uint2*)(sm + OFF_BHI + bo) = hi;
        *(uint2*)(sm + OFF_BLO + bo) = lo;
    }
    __syncthreads();

#pragma unroll 1
    for (int kt = 0; kt < NKT; kt++) {
        const int s = kt & 1;
        // prefetch next chunk
        if (kt < NKT - 1) {
#pragma unroll
            for (int i = 0; i < 4; i++) {
                av[i] = *(const float4*)(Ag + (size_t)(mb + arow[i]) * NDIM + (kt + 1) * BK + acol);
                bv[i] = *(const float4*)(Bg + (size_t)((kt + 1) * BK + brow[i]) * NDIM + nb + bcol);
            }
        }
        // compute on stage s
        {
            const uint32_t stA = smb + (uint32_t)(s * STAGE_ELEMS) * 2;
#pragma unroll
            for (int ks = 0; ks < 2; ks++) {
                const int k0 = ks * 16;
                uint32_t ahi[2][4], alo[2][4], bhi[4][4], blo[4][4];
#pragma unroll
                for (int msub = 0; msub < 2; msub++) {
                    uint32_t addr = stA +
                        (uint32_t)((wm * 32 + msub * 16 + (lane & 15)) * APAD + k0 + (lane >> 4) * 8) * 2;
                    ldsm4(ahi[msub], addr + OFF_AHI * 2);
                    ldsm4(alo[msub], addr + OFF_ALO * 2);
                }
#pragma unroll
                for (int p = 0; p < 4; p++) {
                    uint32_t addr = stA +
                        (uint32_t)((k0 + (lane & 15)) * BPAD + wn * 64 + p * 16 + (lane >> 4) * 8) * 2;
                    ldsm4t(bhi[p], addr + OFF_BHI * 2);
                    ldsm4t(blo[p], addr + OFF_BLO * 2);
                }
#pragma unroll
                for (int msub = 0; msub < 2; msub++)
#pragma unroll
                    for (int p = 0; p < 4; p++)
#pragma unroll
                        for (int half = 0; half < 2; half++) {
                            const int nsub = p * 2 + half;
                            hmma(acc[msub][nsub], ahi[msub], &bhi[p][half * 2]);
                            hmma(acc[msub][nsub], ahi[msub], &blo[p][half * 2]);
                            hmma(acc[msub][nsub], alo[msub], &bhi[p][half * 2]);
                        }
            }
        }
        // store next chunk into stage s^1
        if (kt < NKT - 1) {
            __nv_bfloat16* st = sm + (s ^ 1) * STAGE_ELEMS;
#pragma unroll
            for (int i = 0; i < 4; i++) {
                float4 va = av[i];
                if (SCALE_A) { va.x *= rv[i]; va.y *= rv[i]; va.z *= rv[i]; va.w *= rv[i]; }
                uint2 hi, lo;
                split4(va, hi, lo);
                int ao = arow[i] * APAD + acol;
                *(uint2*)(st + OFF_AHI + ao) = hi;
                *(uint2*)(st + OFF_ALO + ao) = lo;
                split4(bv[i], hi, lo);
                int bo = brow[i] * BPAD + bcol;
                *(uint2*)(st + OFF_BHI + bo) = hi;
                *(uint2*)(st + OFF_BLO + bo) = lo;
            }
            __syncthreads();
        }
    }

    // ---- epilogue
    const int row0 = mb + wm * 32 + (lane >> 2);
    const int col0 = nb + wn * 64 + (lane & 3) * 2;
#pragma unroll
    for (int msub = 0; msub < 2; msub++)
#pragma unroll
        for (int nsub = 0; nsub < 8; nsub++) {
            float* c0 = Cg + (size_t)(row0 + msub * 16) * NDIM + col0 + nsub * 8;
            float* c1 = c0 + 8 * NDIM;
            if (FUSED) {
                float2 x0 = *(float2*)c0;
                float2 x1 = *(float2*)c1;
                float h0 = acc[msub][nsub][0] + x0.x;
                float h1 = acc[msub][nsub][1] + x0.y;
                float h2 = acc[msub][nsub][2] + x1.x;
                float h3 = acc[msub][nsub][3] + x1.y;
                h0 = (h0 > 0.f) ? h0 : 0.01f * h0;
                h1 = (h1 > 0.f) ? h1 : 0.01f * h1;
                h2 = (h2 > 0.f) ? h2 : 0.01f * h2;
                h3 = (h3 > 0.f) ? h3 : 0.01f * h3;
                *(float2*)c0 = make_float2(h0, h1);
                *(float2*)c1 = make_float2(h2, h3);
            } else {
                *(float2*)c0 = make_float2(acc[msub][nsub][0], acc[msub][nsub][1]);
                *(float2*)c1 = make_float2(acc[msub][nsub][2], acc[msub][nsub][3]);
            }
        }
}

// ---------------------------------------------------------------------------
// GEMM1: z=0: g_e1 = X @ W_l1 ; z=1: out = X @ W_l   (grid 6 x 192 x 2)
// ---------------------------------------------------------------------------
__global__ __launch_bounds__(256)
void gemm1_kernel(const float* __restrict__ X,
                  const float* __restrict__ W_l,
                  const float* __restrict__ W_l1,
                  float* __restrict__ out)
{
    const int nb = blockIdx.x * 128;
    const int mb = blockIdx.y * 128;
    const float* W = blockIdx.z ? W_l : W_l1;
    float* C = blockIdx.z ? out : g_e1;
    gemm_body<false, false>(X, W, nullptr, C, mb, nb);
}

// ---------------------------------------------------------------------------
// GEMM2: out = lrelu( (rinv*adj) @ e1 + out )   (grid 6 x 6 x 32)
// ---------------------------------------------------------------------------
__global__ __launch_bounds__(256)
void gemm2_kernel(const float* __restrict__ adj, float* __restrict__ out)
{
    const int b  = blockIdx.z;
    const int nb = blockIdx.x * 128;
    const int mb = blockIdx.y * 128;
    const size_t bo = (size_t)b * NDIM * NDIM;
    gemm_body<true, true>(adj + bo, g_e1 + bo, g_rinv + b * NDIM + mb, out + bo, mb, nb);
}

// ---------------------------------------------------------------------------
extern "C" void kernel_launch(void* const* d_in, const int* in_sizes, int n_in,
                              void* d_out, int out_size)
{
    const float* X    = (const float*)d_in[0];   // [B, N, D]
    const float* adj  = (const float*)d_in[1];   // [B, N, N]
    const float* W_l  = (const float*)d_in[2];   // [D, D]
    const float* W_l1 = (const float*)d_in[3];   // [D, D]
    float* out = (float*)d_out;

    cudaFuncSetAttribute(gemm1_kernel, cudaFuncAttributeMaxDynamicSharedMemorySize, SMEM_BYTES);
    cudaFuncSetAttribute(gemm2_kernel, cudaFuncAttributeMaxDynamicSharedMemorySize, SMEM_BYTES);

    rowinv_kernel<<<(MTOT + 7) / 8, dim3(32, 8)>>>(adj);
    gemm1_kernel<<<dim3(6, 192, 2), 256, SMEM_BYTES>>>(X, W_l, W_l1, out);
    gemm2_kernel<<<dim3(6, 6, 32), 256, SMEM_BYTES>>>(adj, out);
}

// round 4
// speedup vs baseline: 2.6809x; 1.2619x over previous
#include <cuda_runtime.h>
#include <cuda_bf16.h>
#include <cstdint>

#define BATCH 32
#define NDIM  768
#define MTOT  (BATCH * NDIM)     // 24576
#define BK    32
#define NKT   (NDIM / BK)        // 24

typedef __nv_bfloat16 bf16;

// ---------------------------------------------------------------------------
// Scratch (pre-split operands, bf16)
// ---------------------------------------------------------------------------
__device__ bf16 g_Xhi[(size_t)MTOT * NDIM];
__device__ bf16 g_Xlo[(size_t)MTOT * NDIM];
__device__ bf16 g_Whi[(size_t)2 * NDIM * NDIM];   // [z][k][n], z=0:W_l1 z=1:W_l
__device__ bf16 g_Wlo[(size_t)2 * NDIM * NDIM];
__device__ bf16 g_Adj[(size_t)BATCH * NDIM * NDIM];  // bf16(adj * rinv)
__device__ bf16 g_E1 [(size_t)MTOT * NDIM];          // bf16(X @ W_l1)

// ---------------------------------------------------------------------------
// smem geometry (bf16 elems)
// ---------------------------------------------------------------------------
#define APAD 40
#define BPAD 136
#define A_BYTES (128 * APAD * 2)     // 10240
#define B_BYTES (BK * BPAD * 2)      // 8704

// GEMM1 (3-term): stage = Ahi, Alo, Bhi, Blo
#define S1_AHI 0
#define S1_ALO (A_BYTES)
#define S1_BHI (2 * A_BYTES)
#define S1_BLO (2 * A_BYTES + B_BYTES)
#define S1_BYTES (2 * A_BYTES + 2 * B_BYTES)   // 37888
#define STAGES 3
#define SMEM1 (STAGES * S1_BYTES)              // 113664

// GEMM2 (1-term): stage = Ahi, Bhi
#define S2_AHI 0
#define S2_BHI (A_BYTES)
#define S2_BYTES (A_BYTES + B_BYTES)           // 18944
#define SMEM2 (STAGES * S2_BYTES)              // 56832

// ---------------------------------------------------------------------------
// PTX helpers (plain sm_80+ only)
// ---------------------------------------------------------------------------
__device__ __forceinline__ uint32_t smem_u32(const void* p) {
    uint32_t a;
    asm("{ .reg .u64 t; cvta.to.shared.u64 t, %1; cvt.u32.u64 %0, t; }" : "=r"(a) : "l"(p));
    return a;
}
__device__ __forceinline__ void ldsm4(uint32_t* r, uint32_t addr) {
    asm volatile("ldmatrix.sync.aligned.m8n8.x4.shared.b16 {%0,%1,%2,%3}, [%4];"
                 : "=r"(r[0]), "=r"(r[1]), "=r"(r[2]), "=r"(r[3]) : "r"(addr));
}
__device__ __forceinline__ void ldsm4t(uint32_t* r, uint32_t addr) {
    asm volatile("ldmatrix.sync.aligned.m8n8.x4.trans.shared.b16 {%0,%1,%2,%3}, [%4];"
                 : "=r"(r[0]), "=r"(r[1]), "=r"(r[2]), "=r"(r[3]) : "r"(addr));
}
__device__ __forceinline__ void hmma(float* d, const uint32_t* a, const uint32_t* b) {
    asm volatile("mma.sync.aligned.m16n8k16.row.col.f32.bf16.bf16.f32 "
                 "{%0,%1,%2,%3}, {%4,%5,%6,%7}, {%8,%9}, {%0,%1,%2,%3};"
                 : "+f"(d[0]), "+f"(d[1]), "+f"(d[2]), "+f"(d[3])
                 : "r"(a[0]), "r"(a[1]), "r"(a[2]), "r"(a[3]), "r"(b[0]), "r"(b[1]));
}
__device__ __forceinline__ void cp16(uint32_t dst, const void* src) {
    asm volatile("cp.async.cg.shared.global [%0], [%1], 16;" :: "r"(dst), "l"(src));
}
#define CP_COMMIT() asm volatile("cp.async.commit_group;" ::: "memory")
#define CP_WAIT1()  asm volatile("cp.async.wait_group 1;" ::: "memory")

__device__ __forceinline__ void split1(float x, bf16& h, bf16& l) {
    h = __float2bfloat16(x);
    l = __float2bfloat16(x - __bfloat162float(h));
}

// ---------------------------------------------------------------------------
// Prep kernels
// ---------------------------------------------------------------------------
// adj: rowsum -> rinv -> bf16(adj*rinv). One block (192 thr, float4) per row.
__global__ __launch_bounds__(192)
void adjprep_kernel(const float* __restrict__ adj) {
    int row = blockIdx.x;
    int t   = threadIdx.x;
    const float4 v = ((const float4*)(adj + (size_t)row * NDIM))[t];
    float s = v.x + v.y + v.z + v.w;
    __shared__ float ws[6];
    __shared__ float rsh;
#pragma unroll
    for (int o = 16; o > 0; o >>= 1) s += __shfl_down_sync(0xffffffffu, s, o);
    if ((t & 31) == 0) ws[t >> 5] = s;
    __syncthreads();
    if (t == 0) {
        float tot = ws[0] + ws[1] + ws[2] + ws[3] + ws[4] + ws[5];
        rsh = (tot == 0.f) ? 0.f : (1.f / tot);
    }
    __syncthreads();
    float r = rsh;
    bf16 h0 = __float2bfloat16(v.x * r), h1 = __float2bfloat16(v.y * r);
    bf16 h2 = __float2bfloat16(v.z * r), h3 = __float2bfloat16(v.w * r);
    size_t base = (size_t)row * NDIM + t * 4;
    ((__nv_bfloat162*)(g_Adj + base))[0] = __nv_bfloat162(h0, h1);
    ((__nv_bfloat162*)(g_Adj + base))[1] = __nv_bfloat162(h2, h3);
}

// X split (elementwise float4)
__global__ __launch_bounds__(256)
void splitx_kernel(const float* __restrict__ X) {
    size_t i = ((size_t)blockIdx.x * 256 + threadIdx.x) * 4;
    float4 v = *(const float4*)(X + i);
    bf16 h0, l0, h1, l1, h2, l2, h3, l3;
    split1(v.x, h0, l0); split1(v.y, h1, l1); split1(v.z, h2, l2); split1(v.w, h3, l3);
    ((__nv_bfloat162*)(g_Xhi + i))[0] = __nv_bfloat162(h0, h1);
    ((__nv_bfloat162*)(g_Xhi + i))[1] = __nv_bfloat162(h2, h3);
    ((__nv_bfloat162*)(g_Xlo + i))[0] = __nv_bfloat162(l0, l1);
    ((__nv_bfloat162*)(g_Xlo + i))[1] = __nv_bfloat162(l2, l3);
}

// W split: z=blockIdx.y (0: W_l1, 1: W_l)
__global__ __launch_bounds__(256)
void splitw_kernel(const float* __restrict__ W_l, const float* __restrict__ W_l1) {
    const float* W = blockIdx.y ? W_l : W_l1;
    size_t zoff = (size_t)blockIdx.y * NDIM * NDIM;
    size_t i = ((size_t)blockIdx.x * 256 + threadIdx.x) * 4;
    float4 v = *(const float4*)(W + i);
    bf16 h0, l0, h1, l1, h2, l2, h3, l3;
    split1(v.x, h0, l0); split1(v.y, h1, l1); split1(v.z, h2, l2); split1(v.w, h3, l3);
    ((__nv_bfloat162*)(g_Whi + zoff + i))[0] = __nv_bfloat162(h0, h1);
    ((__nv_bfloat162*)(g_Whi + zoff + i))[1] = __nv_bfloat162(h2, h3);
    ((__nv_bfloat162*)(g_Wlo + zoff + i))[0] = __nv_bfloat162(l0, l1);
    ((__nv_bfloat162*)(g_Wlo + zoff + i))[1] = __nv_bfloat162(l2, l3);
}

// ---------------------------------------------------------------------------
// GEMM1: 3-term. C[mb:+128, nb:+128] = X[mb:, :768] @ W[:768, nb:]
//   z=0: write bf16 to g_E1 ; z=1: write fp32 to out
// 256 thr, 8 warps (4m x 2n), warp tile 32x64, BK=32, 3-stage cp.async.
// ---------------------------------------------------------------------------
__global__ __launch_bounds__(256)
void gemm1_kernel(float* __restrict__ out) {
    extern __shared__ char sm[];
    const uint32_t smb = smem_u32(sm);

    const int z  = blockIdx.z;
    const int nb = blockIdx.x * 128;
    const int mb = blockIdx.y * 128;
    const bf16* Ahi = g_Xhi;
    const bf16* Alo = g_Xlo;
    const bf16* Bhi = g_Whi + (size_t)z * NDIM * NDIM;
    const bf16* Blo = g_Wlo + (size_t)z * NDIM * NDIM;

    const int tid  = threadIdx.x;
    const int lane = tid & 31;
    const int wid  = tid >> 5;
    const int wm   = wid >> 1;
    const int wn   = wid & 1;

    // cp.async mapping
    const int ar  = tid >> 1;                 // A row 0..127
    const int ak  = (tid & 1) * 16;           // A k base
    const int bkr = tid >> 3;                 // B k row 0..31
    const int bn  = (tid & 7) * 16;           // B n base

    auto issue = [&](int kt) {
        const uint32_t st = smb + (kt % STAGES) * S1_BYTES;
        const size_t asrc = (size_t)(mb + ar) * NDIM + kt * BK;
        const size_t bsrc0 = (size_t)(kt * BK + bkr) * NDIM + nb;
#pragma unroll
        for (int c = 0; c < 2; c++) {
            int ko = ak + c * 8;
            uint32_t da = st + (uint32_t)(ar * APAD + ko) * 2;
            cp16(da + S1_AHI, Ahi + asrc + ko);
            cp16(da + S1_ALO, Alo + asrc + ko);
            int no = bn + c * 8;
            uint32_t db = st + (uint32_t)(bkr * BPAD + no) * 2;
            cp16(db + S1_BHI, Bhi + bsrc0 + no);
            cp16(db + S1_BLO, Blo + bsrc0 + no);
        }
        CP_COMMIT();
    };

    float acc[2][8][4];
#pragma unroll
    for (int i = 0; i < 2; i++)
#pragma unroll
        for (int j = 0; j < 8; j++)
#pragma unroll
            for (int q = 0; q < 4; q++) acc[i][j][q] = 0.f;

    issue(0);
    issue(1);

#pragma unroll 1
    for (int kt = 0; kt < NKT; kt++) {
        CP_WAIT1();
        __syncthreads();
        if (kt + 2 < NKT) issue(kt + 2); else CP_COMMIT();

        const uint32_t st = smb + (kt % STAGES) * S1_BYTES;
#pragma unroll
        for (int ks = 0; ks < 2; ks++) {
            const int k0 = ks * 16;
            uint32_t ahi[2][4], alo[2][4], bhi[4][4], blo[4][4];
#pragma unroll
            for (int m = 0; m < 2; m++) {
                uint32_t a = st + (uint32_t)((wm * 32 + m * 16 + (lane & 15)) * APAD
                                             + k0 + (lane >> 4) * 8) * 2;
                ldsm4(ahi[m], a + S1_AHI);
                ldsm4(alo[m], a + S1_ALO);
            }
#pragma unroll
            for (int p = 0; p < 4; p++) {
                uint32_t a = st + (uint32_t)((k0 + (lane & 15)) * BPAD
                                             + wn * 64 + p * 16 + (lane >> 4) * 8) * 2;
                ldsm4t(bhi[p], a + S1_BHI);
                ldsm4t(blo[p], a + S1_BLO);
            }
            // term-major ordering: independent accumulators back-to-back
#pragma unroll
            for (int m = 0; m < 2; m++)
#pragma unroll
                for (int p = 0; p < 4; p++)
#pragma unroll
                    for (int h = 0; h < 2; h++)
                        hmma(acc[m][p * 2 + h], ahi[m], &bhi[p][h * 2]);
#pragma unroll
            for (int m = 0; m < 2; m++)
#pragma unroll
                for (int p = 0; p < 4; p++)
#pragma unroll
                    for (int h = 0; h < 2; h++)
                        hmma(acc[m][p * 2 + h], ahi[m], &blo[p][h * 2]);
#pragma unroll
            for (int m = 0; m < 2; m++)
#pragma unroll
                for (int p = 0; p < 4; p++)
#pragma unroll
                    for (int h = 0; h < 2; h++)
                        hmma(acc[m][p * 2 + h], alo[m], &bhi[p][h * 2]);
        }
    }

    // epilogue
    const int row0 = mb + wm * 32 + (lane >> 2);
    const int col0 = nb + wn * 64 + (lane & 3) * 2;
    if (z == 0) {
#pragma unroll
        for (int m = 0; m < 2; m++)
#pragma unroll
            for (int ns = 0; ns < 8; ns++) {
                bf16* c0 = g_E1 + (size_t)(row0 + m * 16) * NDIM + col0 + ns * 8;
                bf16* c1 = c0 + 8 * NDIM;
                *(__nv_bfloat162*)c0 = __nv_bfloat162(
                    __float2bfloat16(acc[m][ns][0]), __float2bfloat16(acc[m][ns][1]));
                *(__nv_bfloat162*)c1 = __nv_bfloat162(
                    __float2bfloat16(acc[m][ns][2]), __float2bfloat16(acc[m][ns][3]));
            }
    } else {
#pragma unroll
        for (int m = 0; m < 2; m++)
#pragma unroll
            for (int ns = 0; ns < 8; ns++) {
                float* c0 = out + (size_t)(row0 + m * 16) * NDIM + col0 + ns * 8;
                float* c1 = c0 + 8 * NDIM;
                *(float2*)c0 = make_float2(acc[m][ns][0], acc[m][ns][1]);
                *(float2*)c1 = make_float2(acc[m][ns][2], acc[m][ns][3]);
            }
    }
}

// ---------------------------------------------------------------------------
// GEMM2: single-term bf16. out = lrelu( adj_n @ e1 + out ), per batch.
// ---------------------------------------------------------------------------
__global__ __launch_bounds__(256)
void gemm2_kernel(float* __restrict__ out) {
    extern __shared__ char sm[];
    const uint32_t smb = smem_u32(sm);

    const int b  = blockIdx.z;
    const int nb = blockIdx.x * 128;
    const int mb = blockIdx.y * 128;
    const size_t bo = (size_t)b * NDIM * NDIM;
    const bf16* A = g_Adj + bo;
    const bf16* B = g_E1 + bo;

    const int tid  = threadIdx.x;
    const int lane = tid & 31;
    const int wid  = tid >> 5;
    const int wm   = wid >> 1;
    const int wn   = wid & 1;

    const int ar  = tid >> 1;
    const int ak  = (tid & 1) * 16;
    const int bkr = tid >> 3;
    const int bn  = (tid & 7) * 16;

    auto issue = [&](int kt) {
        const uint32_t st = smb + (kt % STAGES) * S2_BYTES;
        const size_t asrc = (size_t)(mb + ar) * NDIM + kt * BK;
        const size_t bsrc0 = (size_t)(kt * BK + bkr) * NDIM + nb;
#pragma unroll
        for (int c = 0; c < 2; c++) {
            int ko = ak + c * 8;
            cp16(st + S2_AHI + (uint32_t)(ar * APAD + ko) * 2, A + asrc + ko);
            int no = bn + c * 8;
            cp16(st + S2_BHI + (uint32_t)(bkr * BPAD + no) * 2, B + bsrc0 + no);
        }
        CP_COMMIT();
    };

    float acc[2][8][4];
#pragma unroll
    for (int i = 0; i < 2; i++)
#pragma unroll
        for (int j = 0; j < 8; j++)
#pragma unroll
            for (int q = 0; q < 4; q++) acc[i][j][q] = 0.f;

    issue(0);
    issue(1);

#pragma unroll 1
    for (int kt = 0; kt < NKT; kt++) {
        CP_WAIT1();
        __syncthreads();
        if (kt + 2 < NKT) issue(kt + 2); else CP_COMMIT();

        const uint32_t st = smb + (kt % STAGES) * S2_BYTES;
#pragma unroll
        for (int ks = 0; ks < 2; ks++) {
            const int k0 = ks * 16;
            uint32_t ahi[2][4], bhi[4][4];
#pragma unroll
            for (int m = 0; m < 2; m++) {
                uint32_t a = st + S2_AHI + (uint32_t)((wm * 32 + m * 16 + (lane & 15)) * APAD
                                                      + k0 + (lane >> 4) * 8) * 2;
                ldsm4(ahi[m], a);
            }
#pragma unroll
            for (int p = 0; p < 4; p++) {
                uint32_t a = st + S2_BHI + (uint32_t)((k0 + (lane & 15)) * BPAD
                                                      + wn * 64 + p * 16 + (lane >> 4) * 8) * 2;
                ldsm4t(bhi[p], a);
            }
#pragma unroll
            for (int m = 0; m < 2; m++)
#pragma unroll
                for (int p = 0; p < 4; p++)
#pragma unroll
                    for (int h = 0; h < 2; h++)
                        hmma(acc[m][p * 2 + h], ahi[m], &bhi[p][h * 2]);
        }
    }

    // fused epilogue: read X1 (in out), add, leaky-relu, write
    const int row0 = mb + wm * 32 + (lane >> 2);
    const int col0 = nb + wn * 64 + (lane & 3) * 2;
#pragma unroll
    for (int m = 0; m < 2; m++)
#pragma unroll
        for (int ns = 0; ns < 8; ns++) {
            float* c0 = out + bo + (size_t)(row0 + m * 16) * NDIM + col0 + ns * 8;
            float* c1 = c0 + 8 * NDIM;
            float2 x0 = *(float2*)c0;
            float2 x1 = *(float2*)c1;
            float h0 = acc[m][ns][0] + x0.x;
            float h1 = acc[m][ns][1] + x0.y;
            float h2 = acc[m][ns][2] + x1.x;
            float h3 = acc[m][ns][3] + x1.y;
            h0 = (h0 > 0.f) ? h0 : 0.01f * h0;
            h1 = (h1 > 0.f) ? h1 : 0.01f * h1;
            h2 = (h2 > 0.f) ? h2 : 0.01f * h2;
            h3 = (h3 > 0.f) ? h3 : 0.01f * h3;
            *(float2*)c0 = make_float2(h0, h1);
            *(float2*)c1 = make_float2(h2, h3);
        }
}

// ---------------------------------------------------------------------------
extern "C" void kernel_launch(void* const* d_in, const int* in_sizes, int n_in,
                              void* d_out, int out_size)
{
    const float* X    = (const float*)d_in[0];
    const float* adj  = (const float*)d_in[1];
    const float* W_l  = (const float*)d_in[2];
    const float* W_l1 = (const float*)d_in[3];
    float* out = (float*)d_out;

    cudaFuncSetAttribute(gemm1_kernel, cudaFuncAttributeMaxDynamicSharedMemorySize, SMEM1);
    cudaFuncSetAttribute(gemm2_kernel, cudaFuncAttributeMaxDynamicSharedMemorySize, SMEM2);

    adjprep_kernel<<<MTOT, 192>>>(adj);
    splitx_kernel<<<(MTOT * NDIM) / 1024, 256>>>(X);
    splitw_kernel<<<dim3((NDIM * NDIM) / 1024, 2), 256>>>(W_l, W_l1);
    gemm1_kernel<<<dim3(6, 192, 2), 256, SMEM1>>>(out);
    gemm2_kernel<<<dim3(6, 6, 32), 256, SMEM2>>>(out);
}

// round 5
// speedup vs baseline: 3.5708x; 1.3320x over previous
#include <cuda_runtime.h>
#include <cuda_bf16.h>
#include <cstdint>

#define BATCH 32
#define NDIM  768
#define MTOT  (BATCH * NDIM)     // 24576
#define BK    32
#define NKT   (NDIM / BK)        // 24

typedef __nv_bfloat16 bf16;

__device__ bf16 g_Xhi[(size_t)MTOT * NDIM];
__device__ bf16 g_Xlo[(size_t)MTOT * NDIM];
__device__ bf16 g_Wl_hi[(size_t)NDIM * NDIM];
__device__ bf16 g_Wl_lo[(size_t)NDIM * NDIM];
__device__ bf16 g_Wl1_hi[(size_t)NDIM * NDIM];
__device__ bf16 g_Adj[(size_t)BATCH * NDIM * NDIM];
__device__ bf16 g_E1 [(size_t)MTOT * NDIM];

#define APAD 40
#define BPAD 136
#define A_BYTES (128 * APAD * 2)
#define B_BYTES (BK * BPAD * 2)
#define STAGES 3

#define S3_AHI 0
#define S3_ALO (A_BYTES)
#define S3_BHI (2 * A_BYTES)
#define S3_BLO (2 * A_BYTES + B_BYTES)
#define S3_BYTES (2 * A_BYTES + 2 * B_BYTES)
#define SMEM3 (STAGES * S3_BYTES)

#define S1_AHI 0
#define S1_BHI (A_BYTES)
#define S1_BYTES (A_BYTES + B_BYTES)
#define SMEM1T (STAGES * S1_BYTES)

__device__ __forceinline__ uint32_t smem_u32(const void* p) {
    uint32_t a;
    asm("{ .reg .u64 t; cvta.to.shared.u64 t, %1; cvt.u32.u64 %0, t; }" : "=r"(a) : "l"(p));
    return a;
}
__device__ __forceinline__ void ldsm4(uint32_t* r, uint32_t addr) {
    asm volatile("ldmatrix.sync.aligned.m8n8.x4.shared.b16 {%0,%1,%2,%3}, [%4];"
                 : "=r"(r[0]), "=r"(r[1]), "=r"(r[2]), "=r"(r[3]) : "r"(addr));
}
__device__ __forceinline__ void ldsm4t(uint32_t* r, uint32_t addr) {
    asm volatile("ldmatrix.sync.aligned.m8n8.x4.trans.shared.b16 {%0,%1,%2,%3}, [%4];"
                 : "=r"(r[0]), "=r"(r[1]), "=r"(r[2]), "=r"(r[3]) : "r"(addr));
}
__device__ __forceinline__ void hmma(float* d, const uint32_t* a, const uint32_t* b) {
    asm volatile("mma.sync.aligned.m16n8k16.row.col.f32.bf16.bf16.f32 "
                 "{%0,%1,%2,%3}, {%4,%5,%6,%7}, {%8,%9}, {%0,%1,%2,%3};"
                 : "+f"(d[0]), "+f"(d[1]), "+f"(d[2]), "+f"(d[3])
                 : "r"(a[0]), "r"(a[1]), "r"(a[2]), "r"(a[3]), "r"(b[0]), "r"(b[1]));
}
__device__ __forceinline__ void cp16(uint32_t dst, const void* src) {
    asm volatile("cp.async.cg.shared.global [%0], [%1], 16;" :: "r"(dst), "l"(src));
}
#define CP_COMMIT() asm volatile("cp.async.commit_group;" ::: "memory")
#define CP_WAIT1()  asm volatile("cp.async.wait_group 1;" ::: "memory")

__device__ __forceinline__ void split1(float x, bf16& h, bf16& l) {
    h = __float2bfloat16(x);
    l = __float2bfloat16(x - __bfloat162float(h));
}

// ---------------- prep ----------------
__global__ __launch_bounds__(192)
void adjprep_kernel(const float* __restrict__ adj) {
    int row = blockIdx.x;
    int t   = threadIdx.x;
    const float4 v = ((const float4*)(adj + (size_t)row * NDIM))[t];
    float s = v.x + v.y + v.z + v.w;
    __shared__ float ws[6];
    __shared__ float rsh;
#pragma unroll
    for (int o = 16; o > 0; o >>= 1) s += __shfl_down_sync(0xffffffffu, s, o);
    if ((t & 31) == 0) ws[t >> 5] = s;
    __syncthreads();
    if (t == 0) {
        float tot = ws[0] + ws[1] + ws[2] + ws[3] + ws[4] + ws[5];
        rsh = (tot == 0.f) ? 0.f : (1.f / tot);
    }
    __syncthreads();
    float r = rsh;
    size_t base = (size_t)row * NDIM + t * 4;
    ((__nv_bfloat162*)(g_Adj + base))[0] =
        __nv_bfloat162(__float2bfloat16(v.x * r), __float2bfloat16(v.y * r));
    ((__nv_bfloat162*)(g_Adj + base))[1] =
        __nv_bfloat162(__float2bfloat16(v.z * r), __float2bfloat16(v.w * r));
}

__global__ __launch_bounds__(256)
void splitx_kernel(const float* __restrict__ X) {
    size_t i = ((size_t)blockIdx.x * 256 + threadIdx.x) * 4;
    float4 v = *(const float4*)(X + i);
    bf16 h0, l0, h1, l1, h2, l2, h3, l3;
    split1(v.x, h0, l0); split1(v.y, h1, l1); split1(v.z, h2, l2); split1(v.w, h3, l3);
    ((__nv_bfloat162*)(g_Xhi + i))[0] = __nv_bfloat162(h0, h1);
    ((__nv_bfloat162*)(g_Xhi + i))[1] = __nv_bfloat162(h2, h3);
    ((__nv_bfloat162*)(g_Xlo + i))[0] = __nv_bfloat162(l0, l1);
    ((__nv_bfloat162*)(g_Xlo + i))[1] = __nv_bfloat162(l2, l3);
}

__global__ __launch_bounds__(256)
void splitwl_kernel(const float* __restrict__ W_l) {
    size_t i = ((size_t)blockIdx.x * 256 + threadIdx.x) * 4;
    float4 v = *(const float4*)(W_l + i);
    bf16 h0, l0, h1, l1, h2, l2, h3, l3;
    split1(v.x, h0, l0); split1(v.y, h1, l1); split1(v.z, h2, l2); split1(v.w, h3, l3);
    ((__nv_bfloat162*)(g_Wl_hi + i))[0] = __nv_bfloat162(h0, h1);
    ((__nv_bfloat162*)(g_Wl_hi + i))[1] = __nv_bfloat162(h2, h3);
    ((__nv_bfloat162*)(g_Wl_lo + i))[0] = __nv_bfloat162(l0, l1);
    ((__nv_bfloat162*)(g_Wl_lo + i))[1] = __nv_bfloat162(l2, l3);
}

__global__ __launch_bounds__(256)
void splitw1_kernel(const float* __restrict__ W_l1) {
    size_t i = ((size_t)blockIdx.x * 256 + threadIdx.x) * 4;
    float4 v = *(const float4*)(W_l1 + i);
    ((__nv_bfloat162*)(g_Wl1_hi + i))[0] =
        __nv_bfloat162(__float2bfloat16(v.x), __float2bfloat16(v.y));
    ((__nv_bfloat162*)(g_Wl1_hi + i))[1] =
        __nv_bfloat162(__float2bfloat16(v.z), __float2bfloat16(v.w));
}

// ---------------- 3-term GEMM: out = X @ W_l (fp32) ----------------
__global__ __launch_bounds__(256, 1)
void gemm3_kernel(float* __restrict__ out) {
    extern __shared__ char sm[];
    const uint32_t smb = smem_u32(sm);

    const int nb = blockIdx.x * 128;
    const int mb = blockIdx.y * 128;
    const int tid  = threadIdx.x;
    const int lane = tid & 31;
    const int wid  = tid >> 5;
    const int wm   = wid >> 1;
    const int wn   = wid & 1;
    const int ar  = tid >> 1;
    const int ak  = (tid & 1) * 16;
    const int bkr = tid >> 3;
    const int bn  = (tid & 7) * 16;

    auto issue = [&](int kt) {
        const uint32_t st = smb + (kt % STAGES) * S3_BYTES;
        const size_t asrc = (size_t)(mb + ar) * NDIM + kt * BK;
        const size_t bsrc = (size_t)(kt * BK + bkr) * NDIM + nb;
#pragma unroll
        for (int c = 0; c < 2; c++) {
            int ko = ak + c * 8;
            uint32_t da = st + (uint32_t)(ar * APAD + ko) * 2;
            cp16(da + S3_AHI, g_Xhi + asrc + ko);
            cp16(da + S3_ALO, g_Xlo + asrc + ko);
            int no = bn + c * 8;
            uint32_t db = st + (uint32_t)(bkr * BPAD + no) * 2;
            cp16(db + S3_BHI, g_Wl_hi + bsrc + no);
            cp16(db + S3_BLO, g_Wl_lo + bsrc + no);
        }
        CP_COMMIT();
    };

    float acc[2][8][4];
#pragma unroll
    for (int i = 0; i < 2; i++)
#pragma unroll
        for (int j = 0; j < 8; j++)
#pragma unroll
            for (int q = 0; q < 4; q++) acc[i][j][q] = 0.f;

    issue(0);
    issue(1);

#pragma unroll 1
    for (int kt = 0; kt < NKT; kt++) {
        CP_WAIT1();
        __syncthreads();
        if (kt + 2 < NKT) issue(kt + 2); else CP_COMMIT();

        const uint32_t st = smb + (kt % STAGES) * S3_BYTES;
        uint32_t ahi[2][2][4], alo[2][2][4], bhi[2][4][4], blo[2][4][4];
#pragma unroll
        for (int ks = 0; ks < 2; ks++) {
            const int k0 = ks * 16;
#pragma unroll
            for (int m = 0; m < 2; m++) {
                uint32_t a = st + (uint32_t)((wm * 32 + m * 16 + (lane & 15)) * APAD
                                             + k0 + (lane >> 4) * 8) * 2;
                ldsm4(ahi[ks][m], a + S3_AHI);
                ldsm4(alo[ks][m], a + S3_ALO);
            }
#pragma unroll
            for (int p = 0; p < 4; p++) {
                uint32_t a = st + (uint32_t)((k0 + (lane & 15)) * BPAD
                                             + wn * 64 + p * 16 + (lane >> 4) * 8) * 2;
                ldsm4t(bhi[ks][p], a + S3_BHI);
                ldsm4t(blo[ks][p], a + S3_BLO);
            }
        }
#pragma unroll
        for (int ks = 0; ks < 2; ks++) {
#pragma unroll
            for (int m = 0; m < 2; m++)
#pragma unroll
                for (int p = 0; p < 4; p++)
#pragma unroll
                    for (int h = 0; h < 2; h++)
                        hmma(acc[m][p * 2 + h], ahi[ks][m], &bhi[ks][p][h * 2]);
#pragma unroll
            for (int m = 0; m < 2; m++)
#pragma unroll
                for (int p = 0; p < 4; p++)
#pragma unroll
                    for (int h = 0; h < 2; h++)
                        hmma(acc[m][p * 2 + h], ahi[ks][m], &blo[ks][p][h * 2]);
#pragma unroll
            for (int m = 0; m < 2; m++)
#pragma unroll
                for (int p = 0; p < 4; p++)
#pragma unroll
                    for (int h = 0; h < 2; h++)
                        hmma(acc[m][p * 2 + h], alo[ks][m], &bhi[ks][p][h * 2]);
        }
    }

    const int row0 = mb + wm * 32 + (lane >> 2);
    const int col0 = nb + wn * 64 + (lane & 3) * 2;
#pragma unroll
    for (int m = 0; m < 2; m++)
#pragma unroll
        for (int ns = 0; ns < 8; ns++) {
            float* c0 = out + (size_t)(row0 + m * 16) * NDIM + col0 + ns * 8;
            float* c1 = c0 + 8 * NDIM;
            *(float2*)c0 = make_float2(acc[m][ns][0], acc[m][ns][1]);
            *(float2*)c1 = make_float2(acc[m][ns][2], acc[m][ns][3]);
        }
}

// ---------------- 1-term GEMM body ----------------
template<int EPI>
__device__ __forceinline__ void gemm1t_body(
    const bf16* __restrict__ A, const bf16* __restrict__ B,
    float* __restrict__ outF, bf16* __restrict__ outH,
    int mb, int nb)
{
    extern __shared__ char sm[];
    const uint32_t smb = smem_u32(sm);

    const int tid  = threadIdx.x;
    const int lane = tid & 31;
    const int wid  = tid >> 5;
    const int wm   = wid >> 1;
    const int wn   = wid & 1;
    const int ar  = tid >> 1;
    const int ak  = (tid & 1) * 16;
    const int bkr = tid >> 3;
    const int bn  = (tid & 7) * 16;

    auto issue = [&](int kt) {
        const uint32_t st = smb + (kt % STAGES) * S1_BYTES;
        const size_t asrc = (size_t)(mb + ar) * NDIM + kt * BK;
        const size_t bsrc = (size_t)(kt * BK + bkr) * NDIM + nb;
#pragma unroll
        for (int c = 0; c < 2; c++) {
            int ko = ak + c * 8;
            cp16(st + S1_AHI + (uint32_t)(ar * APAD + ko) * 2, A + asrc + ko);
            int no = bn + c * 8;
            cp16(st + S1_BHI + (uint32_t)(bkr * BPAD + no) * 2, B + bsrc + no);
        }
        CP_COMMIT();
    };

    float acc[2][8][4];
#pragma unroll
    for (int i = 0; i < 2; i++)
#pragma unroll
        for (int j = 0; j < 8; j++)
#pragma unroll
            for (int q = 0; q < 4; q++) acc[i][j][q] = 0.f;

    issue(0);
    issue(1);

#pragma unroll 1
    for (int kt = 0; kt < NKT; kt++) {
        CP_WAIT1();
        __syncthreads();
        if (kt + 2 < NKT) issue(kt + 2); else CP_COMMIT();

        const uint32_t st = smb + (kt % STAGES) * S1_BYTES;
#pragma unroll
        for (int ks = 0; ks < 2; ks++) {
            const int k0 = ks * 16;
            uint32_t ahi[2][4], bhi[4][4];
#pragma unroll
            for (int m = 0; m < 2; m++) {
                uint32_t a = st + S1_AHI + (uint32_t)((wm * 32 + m * 16 + (lane & 15)) * APAD
                                                      + k0 + (lane >> 4) * 8) * 2;
                ldsm4(ahi[m], a);
            }
#pragma unroll
            for (int p = 0; p < 4; p++) {
                uint32_t a = st + S1_BHI + (uint32_t)((k0 + (lane & 15)) * BPAD
                                                      + wn * 64 + p * 16 + (lane >> 4) * 8) * 2;
                ldsm4t(bhi[p], a);
            }
#pragma unroll
            for (int m = 0; m < 2; m++)
#pragma unroll
                for (int p = 0; p < 4; p++)
#pragma unroll
                    for (int h = 0; h < 2; h++)
                        hmma(acc[m][p * 2 + h], ahi[m], &bhi[p][h * 2]);
        }
    }

    const int row0 = mb + wm * 32 + (lane >> 2);
    const int col0 = nb + wn * 64 + (lane & 3) * 2;
    if (EPI == 0) {
#pragma unroll
        for (int m = 0; m < 2; m++)
#pragma unroll
            for (int ns = 0; ns < 8; ns++) {
                bf16* c0 = outH + (size_t)(row0 + m * 16) * NDIM + col0 + ns * 8;
                bf16* c1 = c0 + 8 * NDIM;
                *(__nv_bfloat162*)c0 = __nv_bfloat162(
                    __float2bfloat16(acc[m][ns][0]), __float2bfloat16(acc[m][ns][1]));
                *(__nv_bfloat162*)c1 = __nv_bfloat162(
                    __float2bfloat16(acc[m][ns][2]), __float2bfloat16(acc[m][ns][3]));
            }
    } else {
#pragma unroll
        for (int m = 0; m < 2; m++)
#pragma unroll
            for (int ns = 0; ns < 8; ns++) {
                float* c0 = outF + (size_t)(row0 + m * 16) * NDIM + col0 + ns * 8;
                float* c1 = c0 + 8 * NDIM;
                float2 x0 = *(float2*)c0;
                float2 x1 = *(float2*)c1;
                float h0 = acc[m][ns][0] + x0.x;
                float h1 = acc[m][ns][1] + x0.y;
                float h2 = acc[m][ns][2] + x1.x;
                float h3 = acc[m][ns][3] + x1.y;
                h0 = (h0 > 0.f) ? h0 : 0.01f * h0;
                h1 = (h1 > 0.f) ? h1 : 0.01f * h1;
                h2 = (h2 > 0.f) ? h2 : 0.01f * h2;
                h3 = (h3 > 0.f) ? h3 : 0.01f * h3;
                *(float2*)c0 = make_float2(h0, h1);
                *(float2*)c1 = make_float2(h2, h3);
            }
    }
}

__global__ __launch_bounds__(256, 2)
void gemmE1_kernel() {
    gemm1t_body<0>(g_Xhi, g_Wl1_hi, nullptr, g_E1, blockIdx.y * 128, blockIdx.x * 128);
}

__global__ __launch_bounds__(256, 2)
void gemmAgg_kernel(float* __restrict__ out) {
    const size_t bo = (size_t)blockIdx.z * NDIM * NDIM;
    gemm1t_body<1>(g_Adj + bo, g_E1 + bo, out + bo, nullptr,
                   blockIdx.y * 128, blockIdx.x * 128);
}

// ---------------------------------------------------------------------------
extern "C" void kernel_launch(void* const* d_in, const int* in_sizes, int n_in,
                              void* d_out, int out_size)
{
    const float* X    = (const float*)d_in[0];
    const float* adj  = (const float*)d_in[1];
    const float* W_l  = (const float*)d_in[2];
    const float* W_l1 = (const float*)d_in[3];
    float* out = (float*)d_out;

    cudaFuncSetAttribute(gemm3_kernel,   cudaFuncAttributeMaxDynamicSharedMemorySize, SMEM3);
    cudaFuncSetAttribute(gemmE1_kernel,  cudaFuncAttributeMaxDynamicSharedMemorySize, SMEM1T);
    cudaFuncSetAttribute(gemmAgg_kernel, cudaFuncAttributeMaxDynamicSharedMemorySize, SMEM1T);

    adjprep_kernel<<<MTOT, 192>>>(adj);
    splitx_kernel<<<(MTOT * NDIM) / 1024, 256>>>(X);
    splitwl_kernel<<<(NDIM * NDIM) / 1024, 256>>>(W_l);
    splitw1_kernel<<<(NDIM * NDIM) / 1024, 256>>>(W_l1);

    gemm3_kernel<<<dim3(6, 192), 256, SMEM3>>>(out);
    gemmE1_kernel<<<dim3(6, 192), 256, SMEM1T>>>();
    gemmAgg_kernel<<<dim3(6, 6, 32), 256, SMEM1T>>>(out);
}

// round 6
// speedup vs baseline: 3.8567x; 1.0800x over previous
#include <cuda_runtime.h>
#include <cuda_bf16.h>
#include <cstdint>

#define BATCH 32
#define NDIM  768
#define MTOT  (BATCH * NDIM)     // 24576
#define BK    32
#define NKT   (NDIM / BK)        // 24

typedef __nv_bfloat16 bf16;

__device__ bf16 g_Xhi[(size_t)MTOT * NDIM];
__device__ bf16 g_Xlo[(size_t)MTOT * NDIM];
__device__ bf16 g_Wl_hi[(size_t)NDIM * NDIM];
__device__ bf16 g_Wl_lo[(size_t)NDIM * NDIM];
__device__ bf16 g_Wl1_hi[(size_t)NDIM * NDIM];
__device__ bf16 g_Adj[(size_t)BATCH * NDIM * NDIM];
__device__ bf16 g_E1 [(size_t)MTOT * NDIM];

#define APAD 40
#define BPAD 136
#define A_BYTES (128 * APAD * 2)
#define B_BYTES (BK * BPAD * 2)

// 3-term kernel: 2 stages, Ahi/Alo/Bhi/Blo per stage
#define S3_AHI 0
#define S3_ALO (A_BYTES)
#define S3_BHI (2 * A_BYTES)
#define S3_BLO (2 * A_BYTES + B_BYTES)
#define S3_BYTES (2 * A_BYTES + 2 * B_BYTES)   // 37888
#define SMEM3 (2 * S3_BYTES)                   // 75776 -> 2 CTAs/SM

// 1-term kernels: 3 stages, Ahi/Bhi per stage
#define S1_AHI 0
#define S1_BHI (A_BYTES)
#define S1_BYTES (A_BYTES + B_BYTES)           // 18944
#define SMEM1T (3 * S1_BYTES)                  // 56832 -> 2 CTAs/SM

__device__ __forceinline__ uint32_t smem_u32(const void* p) {
    uint32_t a;
    asm("{ .reg .u64 t; cvta.to.shared.u64 t, %1; cvt.u32.u64 %0, t; }" : "=r"(a) : "l"(p));
    return a;
}
__device__ __forceinline__ void ldsm4(uint32_t* r, uint32_t addr) {
    asm volatile("ldmatrix.sync.aligned.m8n8.x4.shared.b16 {%0,%1,%2,%3}, [%4];"
                 : "=r"(r[0]), "=r"(r[1]), "=r"(r[2]), "=r"(r[3]) : "r"(addr));
}
__device__ __forceinline__ void ldsm4t(uint32_t* r, uint32_t addr) {
    asm volatile("ldmatrix.sync.aligned.m8n8.x4.trans.shared.b16 {%0,%1,%2,%3}, [%4];"
                 : "=r"(r[0]), "=r"(r[1]), "=r"(r[2]), "=r"(r[3]) : "r"(addr));
}
__device__ __forceinline__ void hmma(float* d, const uint32_t* a, const uint32_t* b) {
    asm volatile("mma.sync.aligned.m16n8k16.row.col.f32.bf16.bf16.f32 "
                 "{%0,%1,%2,%3}, {%4,%5,%6,%7}, {%8,%9}, {%0,%1,%2,%3};"
                 : "+f"(d[0]), "+f"(d[1]), "+f"(d[2]), "+f"(d[3])
                 : "r"(a[0]), "r"(a[1]), "r"(a[2]), "r"(a[3]), "r"(b[0]), "r"(b[1]));
}
__device__ __forceinline__ void cp16(uint32_t dst, const void* src) {
    asm volatile("cp.async.cg.shared.global [%0], [%1], 16;" :: "r"(dst), "l"(src));
}
#define CP_COMMIT() asm volatile("cp.async.commit_group;" ::: "memory")
#define CP_WAIT1()  asm volatile("cp.async.wait_group 1;" ::: "memory")

__device__ __forceinline__ void split1(float x, bf16& h, bf16& l) {
    h = __float2bfloat16(x);
    l = __float2bfloat16(x - __bfloat162float(h));
}

// ---------------- prep ----------------
__global__ __launch_bounds__(192)
void adjprep_kernel(const float* __restrict__ adj) {
    int row = blockIdx.x;
    int t   = threadIdx.x;
    const float4 v = ((const float4*)(adj + (size_t)row * NDIM))[t];
    float s = v.x + v.y + v.z + v.w;
    __shared__ float ws[6];
    __shared__ float rsh;
#pragma unroll
    for (int o = 16; o > 0; o >>= 1) s += __shfl_down_sync(0xffffffffu, s, o);
    if ((t & 31) == 0) ws[t >> 5] = s;
    __syncthreads();
    if (t == 0) {
        float tot = ws[0] + ws[1] + ws[2] + ws[3] + ws[4] + ws[5];
        rsh = (tot == 0.f) ? 0.f : (1.f / tot);
    }
    __syncthreads();
    float r = rsh;
    size_t base = (size_t)row * NDIM + t * 4;
    ((__nv_bfloat162*)(g_Adj + base))[0] =
        __nv_bfloat162(__float2bfloat16(v.x * r), __float2bfloat16(v.y * r));
    ((__nv_bfloat162*)(g_Adj + base))[1] =
        __nv_bfloat162(__float2bfloat16(v.z * r), __float2bfloat16(v.w * r));
}

__global__ __launch_bounds__(256)
void splitx_kernel(const float* __restrict__ X) {
    size_t i = ((size_t)blockIdx.x * 256 + threadIdx.x) * 4;
    float4 v = *(const float4*)(X + i);
    bf16 h0, l0, h1, l1, h2, l2, h3, l3;
    split1(v.x, h0, l0); split1(v.y, h1, l1); split1(v.z, h2, l2); split1(v.w, h3, l3);
    ((__nv_bfloat162*)(g_Xhi + i))[0] = __nv_bfloat162(h0, h1);
    ((__nv_bfloat162*)(g_Xhi + i))[1] = __nv_bfloat162(h2, h3);
    ((__nv_bfloat162*)(g_Xlo + i))[0] = __nv_bfloat162(l0, l1);
    ((__nv_bfloat162*)(g_Xlo + i))[1] = __nv_bfloat162(l2, l3);
}

__global__ __launch_bounds__(256)
void splitwl_kernel(const float* __restrict__ W_l) {
    size_t i = ((size_t)blockIdx.x * 256 + threadIdx.x) * 4;
    float4 v = *(const float4*)(W_l + i);
    bf16 h0, l0, h1, l1, h2, l2, h3, l3;
    split1(v.x, h0, l0); split1(v.y, h1, l1); split1(v.z, h2, l2); split1(v.w, h3, l3);
    ((__nv_bfloat162*)(g_Wl_hi + i))[0] = __nv_bfloat162(h0, h1);
    ((__nv_bfloat162*)(g_Wl_hi + i))[1] = __nv_bfloat162(h2, h3);
    ((__nv_bfloat162*)(g_Wl_lo + i))[0] = __nv_bfloat162(l0, l1);
    ((__nv_bfloat162*)(g_Wl_lo + i))[1] = __nv_bfloat162(l2, l3);
}

__global__ __launch_bounds__(256)
void splitw1_kernel(const float* __restrict__ W_l1) {
    size_t i = ((size_t)blockIdx.x * 256 + threadIdx.x) * 4;
    float4 v = *(const float4*)(W_l1 + i);
    ((__nv_bfloat162*)(g_Wl1_hi + i))[0] =
        __nv_bfloat162(__float2bfloat16(v.x), __float2bfloat16(v.y));
    ((__nv_bfloat162*)(g_Wl1_hi + i))[1] =
        __nv_bfloat162(__float2bfloat16(v.z), __float2bfloat16(v.w));
}

// ---------------- 3-term GEMM: out = X @ W_l (fp32), 2 CTAs/SM ----------------
__global__ __launch_bounds__(256, 2)
void gemm3_kernel(float* __restrict__ out) {
    extern __shared__ char sm[];
    const uint32_t smb = smem_u32(sm);

    const int nb = blockIdx.x * 128;
    const int mb = blockIdx.y * 128;
    const int tid  = threadIdx.x;
    const int lane = tid & 31;
    const int wid  = tid >> 5;
    const int wm   = wid >> 1;
    const int wn   = wid & 1;
    const int ar  = tid >> 1;
    const int ak  = (tid & 1) * 16;
    const int bkr = tid >> 3;
    const int bn  = (tid & 7) * 16;

    auto issue = [&](int kt) {
        const uint32_t st = smb + (kt & 1) * S3_BYTES;
        const size_t asrc = (size_t)(mb + ar) * NDIM + kt * BK;
        const size_t bsrc = (size_t)(kt * BK + bkr) * NDIM + nb;
#pragma unroll
        for (int c = 0; c < 2; c++) {
            int ko = ak + c * 8;
            uint32_t da = st + (uint32_t)(ar * APAD + ko) * 2;
            cp16(da + S3_AHI, g_Xhi + asrc + ko);
            cp16(da + S3_ALO, g_Xlo + asrc + ko);
            int no = bn + c * 8;
            uint32_t db = st + (uint32_t)(bkr * BPAD + no) * 2;
            cp16(db + S3_BHI, g_Wl_hi + bsrc + no);
            cp16(db + S3_BLO, g_Wl_lo + bsrc + no);
        }
        CP_COMMIT();
    };

    float acc[2][8][4];
#pragma unroll
    for (int i = 0; i < 2; i++)
#pragma unroll
        for (int j = 0; j < 8; j++)
#pragma unroll
            for (int q = 0; q < 4; q++) acc[i][j][q] = 0.f;

    issue(0);

#pragma unroll 1
    for (int kt = 0; kt < NKT; kt++) {
        if (kt + 1 < NKT) issue(kt + 1); else CP_COMMIT();
        CP_WAIT1();
        __syncthreads();

        const uint32_t st = smb + (kt & 1) * S3_BYTES;
#pragma unroll
        for (int ks = 0; ks < 2; ks++) {
            const int k0 = ks * 16;
            const uint32_t aaddr = st + (uint32_t)((wm * 32 + (lane & 15)) * APAD
                                                   + k0 + (lane >> 4) * 8) * 2;
            const uint32_t baddr = st + (uint32_t)((k0 + (lane & 15)) * BPAD
                                                   + wn * 64 + (lane >> 4) * 8) * 2;
            // lifetime-ordered terms: peak live frags = ahi+bhi+alo = 32 regs
            uint32_t ahi[2][4];
#pragma unroll
            for (int m = 0; m < 2; m++)
                ldsm4(ahi[m], aaddr + S3_AHI + (uint32_t)(m * 16 * APAD) * 2);
            {
                uint32_t bhi[4][4];
#pragma unroll
                for (int p = 0; p < 4; p++)
                    ldsm4t(bhi[p], baddr + S3_BHI + (uint32_t)(p * 16) * 2);
                // term1: ahi x bhi
#pragma unroll
                for (int m = 0; m < 2; m++)
#pragma unroll
                    for (int p = 0; p < 4; p++)
#pragma unroll
                        for (int h = 0; h < 2; h++)
                            hmma(acc[m][p * 2 + h], ahi[m], &bhi[p][h * 2]);
                // term3: alo x bhi  (alo lives only here)
                {
                    uint32_t alo[2][4];
#pragma unroll
                    for (int m = 0; m < 2; m++)
                        ldsm4(alo[m], aaddr + S3_ALO + (uint32_t)(m * 16 * APAD) * 2);
#pragma unroll
                    for (int m = 0; m < 2; m++)
#pragma unroll
                        for (int p = 0; p < 4; p++)
#pragma unroll
                            for (int h = 0; h < 2; h++)
                                hmma(acc[m][p * 2 + h], alo[m], &bhi[p][h * 2]);
                }
            }
            // term2: ahi x blo  (bhi dead, blo reuses its space)
            {
                uint32_t blo[4][4];
#pragma unroll
                for (int p = 0; p < 4; p++)
                    ldsm4t(blo[p], baddr + S3_BLO + (uint32_t)(p * 16) * 2);
#pragma unroll
                for (int m = 0; m < 2; m++)
#pragma unroll
                    for (int p = 0; p < 4; p++)
#pragma unroll
                        for (int h = 0; h < 2; h++)
                            hmma(acc[m][p * 2 + h], ahi[m], &blo[p][h * 2]);
            }
        }
        __syncthreads();   // stage fully consumed before it is re-filled
    }

    const int row0 = mb + wm * 32 + (lane >> 2);
    const int col0 = nb + wn * 64 + (lane & 3) * 2;
#pragma unroll
    for (int m = 0; m < 2; m++)
#pragma unroll
        for (int ns = 0; ns < 8; ns++) {
            float* c0 = out + (size_t)(row0 + m * 16) * NDIM + col0 + ns * 8;
            float* c1 = c0 + 8 * NDIM;
            *(float2*)c0 = make_float2(acc[m][ns][0], acc[m][ns][1]);
            *(float2*)c1 = make_float2(acc[m][ns][2], acc[m][ns][3]);
        }
}

// ---------------- 1-term GEMM body (3-stage, 2 CTAs/SM) ----------------
template<int EPI>
__device__ __forceinline__ void gemm1t_body(
    const bf16* __restrict__ A, const bf16* __restrict__ B,
    float* __restrict__ outF, bf16* __restrict__ outH,
    int mb, int nb)
{
    extern __shared__ char sm[];
    const uint32_t smb = smem_u32(sm);

    const int tid  = threadIdx.x;
    const int lane = tid & 31;
    const int wid  = tid >> 5;
    const int wm   = wid >> 1;
    const int wn   = wid & 1;
    const int ar  = tid >> 1;
    const int ak  = (tid & 1) * 16;
    const int bkr = tid >> 3;
    const int bn  = (tid & 7) * 16;

    auto issue = [&](int kt) {
        const uint32_t st = smb + (kt % 3) * S1_BYTES;
        const size_t asrc = (size_t)(mb + ar) * NDIM + kt * BK;
        const size_t bsrc = (size_t)(kt * BK + bkr) * NDIM + nb;
#pragma unroll
        for (int c = 0; c < 2; c++) {
            int ko = ak + c * 8;
            cp16(st + S1_AHI + (uint32_t)(ar * APAD + ko) * 2, A + asrc + ko);
            int no = bn + c * 8;
            cp16(st + S1_BHI + (uint32_t)(bkr * BPAD + no) * 2, B + bsrc + no);
        }
        CP_COMMIT();
    };

    float acc[2][8][4];
#pragma unroll
    for (int i = 0; i < 2; i++)
#pragma unroll
        for (int j = 0; j < 8; j++)
#pragma unroll
            for (int q = 0; q < 4; q++) acc[i][j][q] = 0.f;

    issue(0);
    issue(1);

#pragma unroll 1
    for (int kt = 0; kt < NKT; kt++) {
        CP_WAIT1();
        __syncthreads();
        if (kt + 2 < NKT) issue(kt + 2); else CP_COMMIT();

        const uint32_t st = smb + (kt % 3) * S1_BYTES;
#pragma unroll
        for (int ks = 0; ks < 2; ks++) {
            const int k0 = ks * 16;
            uint32_t ahi[2][4], bhi[4][4];
#pragma unroll
            for (int m = 0; m < 2; m++) {
                uint32_t a = st + S1_AHI + (uint32_t)((wm * 32 + m * 16 + (lane & 15)) * APAD
                                                      + k0 + (lane >> 4) * 8) * 2;
                ldsm4(ahi[m], a);
            }
#pragma unroll
            for (int p = 0; p < 4; p++) {
                uint32_t a = st + S1_BHI + (uint32_t)((k0 + (lane & 15)) * BPAD
                                                      + wn * 64 + p * 16 + (lane >> 4) * 8) * 2;
                ldsm4t(bhi[p], a);
            }
#pragma unroll
            for (int m = 0; m < 2; m++)
#pragma unroll
                for (int p = 0; p < 4; p++)
#pragma unroll
                    for (int h = 0; h < 2; h++)
                        hmma(acc[m][p * 2 + h], ahi[m], &bhi[p][h * 2]);
        }
    }

    const int row0 = mb + wm * 32 + (lane >> 2);
    const int col0 = nb + wn * 64 + (lane & 3) * 2;
    if (EPI == 0) {
#pragma unroll
        for (int m = 0; m < 2; m++)
#pragma unroll
            for (int ns = 0; ns < 8; ns++) {
                bf16* c0 = outH + (size_t)(row0 + m * 16) * NDIM + col0 + ns * 8;
                bf16* c1 = c0 + 8 * NDIM;
                *(__nv_bfloat162*)c0 = __nv_bfloat162(
                    __float2bfloat16(acc[m][ns][0]), __float2bfloat16(acc[m][ns][1]));
                *(__nv_bfloat162*)c1 = __nv_bfloat162(
                    __float2bfloat16(acc[m][ns][2]), __float2bfloat16(acc[m][ns][3]));
            }
    } else {
#pragma unroll
        for (int m = 0; m < 2; m++)
#pragma unroll
            for (int ns = 0; ns < 8; ns++) {
                float* c0 = outF + (size_t)(row0 + m * 16) * NDIM + col0 + ns * 8;
                float* c1 = c0 + 8 * NDIM;
                float2 x0 = *(float2*)c0;
                float2 x1 = *(float2*)c1;
                float h0 = acc[m][ns][0] + x0.x;
                float h1 = acc[m][ns][1] + x0.y;
                float h2 = acc[m][ns][2] + x1.x;
                float h3 = acc[m][ns][3] + x1.y;
                h0 = (h0 > 0.f) ? h0 : 0.01f * h0;
                h1 = (h1 > 0.f) ? h1 : 0.01f * h1;
                h2 = (h2 > 0.f) ? h2 : 0.01f * h2;
                h3 = (h3 > 0.f) ? h3 : 0.01f * h3;
                *(float2*)c0 = make_float2(h0, h1);
                *(float2*)c1 = make_float2(h2, h3);
            }
    }
}

__global__ __launch_bounds__(256, 2)
void gemmE1_kernel() {
    gemm1t_body<0>(g_Xhi, g_Wl1_hi, nullptr, g_E1, blockIdx.y * 128, blockIdx.x * 128);
}

__global__ __launch_bounds__(256, 2)
void gemmAgg_kernel(float* __restrict__ out) {
    const size_t bo = (size_t)blockIdx.z * NDIM * NDIM;
    gemm1t_body<1>(g_Adj + bo, g_E1 + bo, out + bo, nullptr,
                   blockIdx.y * 128, blockIdx.x * 128);
}

// ---------------------------------------------------------------------------
extern "C" void kernel_launch(void* const* d_in, const int* in_sizes, int n_in,
                              void* d_out, int out_size)
{
    const float* X    = (const float*)d_in[0];
    const float* adj  = (const float*)d_in[1];
    const float* W_l  = (const float*)d_in[2];
    const float* W_l1 = (const float*)d_in[3];
    float* out = (float*)d_out;

    cudaFuncSetAttribute(gemm3_kernel,   cudaFuncAttributeMaxDynamicSharedMemorySize, SMEM3);
    cudaFuncSetAttribute(gemmE1_kernel,  cudaFuncAttributeMaxDynamicSharedMemorySize, SMEM1T);
    cudaFuncSetAttribute(gemmAgg_kernel, cudaFuncAttributeMaxDynamicSharedMemorySize, SMEM1T);

    adjprep_kernel<<<MTOT, 192>>>(adj);
    splitx_kernel<<<(MTOT * NDIM) / 1024, 256>>>(X);
    splitwl_kernel<<<(NDIM * NDIM) / 1024, 256>>>(W_l);
    splitw1_kernel<<<(NDIM * NDIM) / 1024, 256>>>(W_l1);

    gemm3_kernel<<<dim3(6, 192), 256, SMEM3>>>(out);
    gemmE1_kernel<<<dim3(6, 192), 256, SMEM1T>>>();
    gemmAgg_kernel<<<dim3(6, 6, 32), 256, SMEM1T>>>(out);
}

// round 7
// speedup vs baseline: 3.9709x; 1.0296x over previous
#include <cuda_runtime.h>
#include <cuda_bf16.h>
#include <cstdint>

#define BATCH 32
#define NDIM  768
#define MTOT  (BATCH * NDIM)     // 24576
#define BK    32
#define NKT3  (NDIM / BK)        // 24 chunks: 3-term X@W_l
#define NKT_T (NKT3 + NDIM / BK) // 36 total: + 12 chunks 1-term Y@W_l1

typedef __nv_bfloat16 bf16;

__device__ bf16 g_Xhi[(size_t)MTOT * NDIM];
__device__ bf16 g_Xlo[(size_t)MTOT * NDIM];
__device__ bf16 g_Wl_hi[(size_t)NDIM * NDIM];
__device__ bf16 g_Wl_lo[(size_t)NDIM * NDIM];
__device__ bf16 g_Wl1_hi[(size_t)NDIM * NDIM];
__device__ bf16 g_Adj[(size_t)BATCH * NDIM * NDIM];
__device__ bf16 g_Y [(size_t)MTOT * NDIM];          // adj_n @ Xhi

#define APAD 40
#define BPAD 136
#define A_BYTES (128 * APAD * 2)
#define B_BYTES (BK * BPAD * 2)

// big GEMM: 2 stages, Ahi/Alo/Bhi/Blo per stage (1-term chunks use Ahi/Bhi only)
#define S3_AHI 0
#define S3_ALO (A_BYTES)
#define S3_BHI (2 * A_BYTES)
#define S3_BLO (2 * A_BYTES + B_BYTES)
#define S3_BYTES (2 * A_BYTES + 2 * B_BYTES)   // 37888
#define SMEM3 (2 * S3_BYTES)                   // 75776 -> 2 CTAs/SM

// aggX: 3 stages, Ahi/Bhi
#define S1_AHI 0
#define S1_BHI (A_BYTES)
#define S1_BYTES (A_BYTES + B_BYTES)           // 18944
#define SMEM1T (3 * S1_BYTES)                  // 56832 -> 2 CTAs/SM

__device__ __forceinline__ uint32_t smem_u32(const void* p) {
    uint32_t a;
    asm("{ .reg .u64 t; cvta.to.shared.u64 t, %1; cvt.u32.u64 %0, t; }" : "=r"(a) : "l"(p));
    return a;
}
__device__ __forceinline__ void ldsm4(uint32_t* r, uint32_t addr) {
    asm volatile("ldmatrix.sync.aligned.m8n8.x4.shared.b16 {%0,%1,%2,%3}, [%4];"
                 : "=r"(r[0]), "=r"(r[1]), "=r"(r[2]), "=r"(r[3]) : "r"(addr));
}
__device__ __forceinline__ void ldsm4t(uint32_t* r, uint32_t addr) {
    asm volatile("ldmatrix.sync.aligned.m8n8.x4.trans.shared.b16 {%0,%1,%2,%3}, [%4];"
                 : "=r"(r[0]), "=r"(r[1]), "=r"(r[2]), "=r"(r[3]) : "r"(addr));
}
__device__ __forceinline__ void hmma(float* d, const uint32_t* a, const uint32_t* b) {
    asm volatile("mma.sync.aligned.m16n8k16.row.col.f32.bf16.bf16.f32 "
                 "{%0,%1,%2,%3}, {%4,%5,%6,%7}, {%8,%9}, {%0,%1,%2,%3};"
                 : "+f"(d[0]), "+f"(d[1]), "+f"(d[2]), "+f"(d[3])
                 : "r"(a[0]), "r"(a[1]), "r"(a[2]), "r"(a[3]), "r"(b[0]), "r"(b[1]));
}
__device__ __forceinline__ void cp16(uint32_t dst, const void* src) {
    asm volatile("cp.async.cg.shared.global [%0], [%1], 16;" :: "r"(dst), "l"(src));
}
#define CP_COMMIT() asm volatile("cp.async.commit_group;" ::: "memory")
#define CP_WAIT1()  asm volatile("cp.async.wait_group 1;" ::: "memory")

__device__ __forceinline__ void split1(float x, bf16& h, bf16& l) {
    h = __float2bfloat16(x);
    l = __float2bfloat16(x - __bfloat162float(h));
}

// ---------------- prep ----------------
__global__ __launch_bounds__(192)
void adjprep_kernel(const float* __restrict__ adj) {
    int row = blockIdx.x;
    int t   = threadIdx.x;
    const float4 v = ((const float4*)(adj + (size_t)row * NDIM))[t];
    float s = v.x + v.y + v.z + v.w;
    __shared__ float ws[6];
    __shared__ float rsh;
#pragma unroll
    for (int o = 16; o > 0; o >>= 1) s += __shfl_down_sync(0xffffffffu, s, o);
    if ((t & 31) == 0) ws[t >> 5] = s;
    __syncthreads();
    if (t == 0) {
        float tot = ws[0] + ws[1] + ws[2] + ws[3] + ws[4] + ws[5];
        rsh = (tot == 0.f) ? 0.f : (1.f / tot);
    }
    __syncthreads();
    float r = rsh;
    size_t base = (size_t)row * NDIM + t * 4;
    ((__nv_bfloat162*)(g_Adj + base))[0] =
        __nv_bfloat162(__float2bfloat16(v.x * r), __float2bfloat16(v.y * r));
    ((__nv_bfloat162*)(g_Adj + base))[1] =
        __nv_bfloat162(__float2bfloat16(v.z * r), __float2bfloat16(v.w * r));
}

__global__ __launch_bounds__(256)
void splitx_kernel(const float* __restrict__ X) {
    size_t i = ((size_t)blockIdx.x * 256 + threadIdx.x) * 4;
    float4 v = *(const float4*)(X + i);
    bf16 h0, l0, h1, l1, h2, l2, h3, l3;
    split1(v.x, h0, l0); split1(v.y, h1, l1); split1(v.z, h2, l2); split1(v.w, h3, l3);
    ((__nv_bfloat162*)(g_Xhi + i))[0] = __nv_bfloat162(h0, h1);
    ((__nv_bfloat162*)(g_Xhi + i))[1] = __nv_bfloat162(h2, h3);
    ((__nv_bfloat162*)(g_Xlo + i))[0] = __nv_bfloat162(l0, l1);
    ((__nv_bfloat162*)(g_Xlo + i))[1] = __nv_bfloat162(l2, l3);
}

__global__ __launch_bounds__(256)
void splitw_kernel(const float* __restrict__ W_l, const float* __restrict__ W_l1) {
    size_t i = ((size_t)blockIdx.x * 256 + threadIdx.x) * 4;
    {
        float4 v = *(const float4*)(W_l + i);
        bf16 h0, l0, h1, l1, h2, l2, h3, l3;
        split1(v.x, h0, l0); split1(v.y, h1, l1); split1(v.z, h2, l2); split1(v.w, h3, l3);
        ((__nv_bfloat162*)(g_Wl_hi + i))[0] = __nv_bfloat162(h0, h1);
        ((__nv_bfloat162*)(g_Wl_hi + i))[1] = __nv_bfloat162(h2, h3);
        ((__nv_bfloat162*)(g_Wl_lo + i))[0] = __nv_bfloat162(l0, l1);
        ((__nv_bfloat162*)(g_Wl_lo + i))[1] = __nv_bfloat162(l2, l3);
    }
    {
        float4 v = *(const float4*)(W_l1 + i);
        ((__nv_bfloat162*)(g_Wl1_hi + i))[0] =
            __nv_bfloat162(__float2bfloat16(v.x), __float2bfloat16(v.y));
        ((__nv_bfloat162*)(g_Wl1_hi + i))[1] =
            __nv_bfloat162(__float2bfloat16(v.z), __float2bfloat16(v.w));
    }
}

// ---------------- aggX: Y = adj_n @ Xhi (1-term, bf16 out) ----------------
__global__ __launch_bounds__(256, 2)
void aggx_kernel() {
    extern __shared__ char sm[];
    const uint32_t smb = smem_u32(sm);

    const int b  = blockIdx.z;
    const int nb = blockIdx.x * 128;
    const int mb = blockIdx.y * 128;
    const size_t bo = (size_t)b * NDIM * NDIM;
    const bf16* A = g_Adj + bo;
    const bf16* B = g_Xhi + bo;

    const int tid  = threadIdx.x;
    const int lane = tid & 31;
    const int wid  = tid >> 5;
    const int wm   = wid >> 1;
    const int wn   = wid & 1;
    const int ar  = tid >> 1;
    const int ak  = (tid & 1) * 16;
    const int bkr = tid >> 3;
    const int bn  = (tid & 7) * 16;

    auto issue = [&](int kt) {
        const uint32_t st = smb + (kt % 3) * S1_BYTES;
        const size_t asrc = (size_t)(mb + ar) * NDIM + kt * BK;
        const size_t bsrc = (size_t)(kt * BK + bkr) * NDIM + nb;
#pragma unroll
        for (int c = 0; c < 2; c++) {
            int ko = ak + c * 8;
            cp16(st + S1_AHI + (uint32_t)(ar * APAD + ko) * 2, A + asrc + ko);
            int no = bn + c * 8;
            cp16(st + S1_BHI + (uint32_t)(bkr * BPAD + no) * 2, B + bsrc + no);
        }
        CP_COMMIT();
    };

    float acc[2][8][4];
#pragma unroll
    for (int i = 0; i < 2; i++)
#pragma unroll
        for (int j = 0; j < 8; j++)
#pragma unroll
            for (int q = 0; q < 4; q++) acc[i][j][q] = 0.f;

    issue(0);
    issue(1);

#pragma unroll 1
    for (int kt = 0; kt < NKT3; kt++) {
        CP_WAIT1();
        __syncthreads();
        if (kt + 2 < NKT3) issue(kt + 2); else CP_COMMIT();

        const uint32_t st = smb + (kt % 3) * S1_BYTES;
#pragma unroll
        for (int ks = 0; ks < 2; ks++) {
            const int k0 = ks * 16;
            uint32_t ahi[2][4], bhi[4][4];
#pragma unroll
            for (int m = 0; m < 2; m++)
                ldsm4(ahi[m], st + S1_AHI + (uint32_t)((wm * 32 + m * 16 + (lane & 15)) * APAD
                                                       + k0 + (lane >> 4) * 8) * 2);
#pragma unroll
            for (int p = 0; p < 4; p++)
                ldsm4t(bhi[p], st + S1_BHI + (uint32_t)((k0 + (lane & 15)) * BPAD
                                                        + wn * 64 + p * 16 + (lane >> 4) * 8) * 2);
#pragma unroll
            for (int m = 0; m < 2; m++)
#pragma unroll
                for (int p = 0; p < 4; p++)
#pragma unroll
                    for (int h = 0; h < 2; h++)
                        hmma(acc[m][p * 2 + h], ahi[m], &bhi[p][h * 2]);
        }
    }

    const int row0 = mb + wm * 32 + (lane >> 2);
    const int col0 = nb + wn * 64 + (lane & 3) * 2;
#pragma unroll
    for (int m = 0; m < 2; m++)
#pragma unroll
        for (int ns = 0; ns < 8; ns++) {
            bf16* c0 = g_Y + bo + (size_t)(row0 + m * 16) * NDIM + col0 + ns * 8;
            bf16* c1 = c0 + 8 * NDIM;
            *(__nv_bfloat162*)c0 = __nv_bfloat162(
                __float2bfloat16(acc[m][ns][0]), __float2bfloat16(acc[m][ns][1]));
            *(__nv_bfloat162*)c1 = __nv_bfloat162(
                __float2bfloat16(acc[m][ns][2]), __float2bfloat16(acc[m][ns][3]));
        }
}

// ---------------- big GEMM: out = lrelu( X@W_l (3-term) + Y@W_l1 (1-term) ) ----------------
__global__ __launch_bounds__(256, 2)
void biggemm_kernel(float* __restrict__ out) {
    extern __shared__ char sm[];
    const uint32_t smb = smem_u32(sm);

    const int nb = blockIdx.x * 128;
    const int mb = blockIdx.y * 128;
    const int tid  = threadIdx.x;
    const int lane = tid & 31;
    const int wid  = tid >> 5;
    const int wm   = wid >> 1;
    const int wn   = wid & 1;
    const int ar  = tid >> 1;
    const int ak  = (tid & 1) * 16;
    const int bkr = tid >> 3;
    const int bn  = (tid & 7) * 16;

    auto issue = [&](int kt) {
        const uint32_t st = smb + (kt & 1) * S3_BYTES;
        if (kt < NKT3) {
            const size_t asrc = (size_t)(mb + ar) * NDIM + kt * BK;
            const size_t bsrc = (size_t)(kt * BK + bkr) * NDIM + nb;
#pragma unroll
            for (int c = 0; c < 2; c++) {
                int ko = ak + c * 8;
                uint32_t da = st + (uint32_t)(ar * APAD + ko) * 2;
                cp16(da + S3_AHI, g_Xhi + asrc + ko);
                cp16(da + S3_ALO, g_Xlo + asrc + ko);
                int no = bn + c * 8;
                uint32_t db = st + (uint32_t)(bkr * BPAD + no) * 2;
                cp16(db + S3_BHI, g_Wl_hi + bsrc + no);
                cp16(db + S3_BLO, g_Wl_lo + bsrc + no);
            }
        } else {
            const int k2 = kt - NKT3;
            const size_t asrc = (size_t)(mb + ar) * NDIM + k2 * BK;
            const size_t bsrc = (size_t)(k2 * BK + bkr) * NDIM + nb;
#pragma unroll
            for (int c = 0; c < 2; c++) {
                int ko = ak + c * 8;
                cp16(st + S3_AHI + (uint32_t)(ar * APAD + ko) * 2, g_Y + asrc + ko);
                int no = bn + c * 8;
                cp16(st + S3_BHI + (uint32_t)(bkr * BPAD + no) * 2, g_Wl1_hi + bsrc + no);
            }
        }
        CP_COMMIT();
    };

    float acc[2][8][4];
#pragma unroll
    for (int i = 0; i < 2; i++)
#pragma unroll
        for (int j = 0; j < 8; j++)
#pragma unroll
            for (int q = 0; q < 4; q++) acc[i][j][q] = 0.f;

    issue(0);

#pragma unroll 1
    for (int kt = 0; kt < NKT_T; kt++) {
        if (kt + 1 < NKT_T) issue(kt + 1); else CP_COMMIT();
        CP_WAIT1();
        __syncthreads();

        const uint32_t st = smb + (kt & 1) * S3_BYTES;
        if (kt < NKT3) {
#pragma unroll
            for (int ks = 0; ks < 2; ks++) {
                const int k0 = ks * 16;
                const uint32_t aaddr = st + (uint32_t)((wm * 32 + (lane & 15)) * APAD
                                                       + k0 + (lane >> 4) * 8) * 2;
                const uint32_t baddr = st + (uint32_t)((k0 + (lane & 15)) * BPAD
                                                       + wn * 64 + (lane >> 4) * 8) * 2;
                uint32_t ahi[2][4];
#pragma unroll
                for (int m = 0; m < 2; m++)
                    ldsm4(ahi[m], aaddr + S3_AHI + (uint32_t)(m * 16 * APAD) * 2);
                {
                    uint32_t bhi[4][4];
#pragma unroll
                    for (int p = 0; p < 4; p++)
                        ldsm4t(bhi[p], baddr + S3_BHI + (uint32_t)(p * 16) * 2);
#pragma unroll
                    for (int m = 0; m < 2; m++)
#pragma unroll
                        for (int p = 0; p < 4; p++)
#pragma unroll
                            for (int h = 0; h < 2; h++)
                                hmma(acc[m][p * 2 + h], ahi[m], &bhi[p][h * 2]);
                    {
                        uint32_t alo[2][4];
#pragma unroll
                        for (int m = 0; m < 2; m++)
                            ldsm4(alo[m], aaddr + S3_ALO + (uint32_t)(m * 16 * APAD) * 2);
#pragma unroll
                        for (int m = 0; m < 2; m++)
#pragma unroll
                            for (int p = 0; p < 4; p++)
#pragma unroll
                                for (int h = 0; h < 2; h++)
                                    hmma(acc[m][p * 2 + h], alo[m], &bhi[p][h * 2]);
                    }
                }
                {
                    uint32_t blo[4][4];
#pragma unroll
                    for (int p = 0; p < 4; p++)
                        ldsm4t(blo[p], baddr + S3_BLO + (uint32_t)(p * 16) * 2);
#pragma unroll
                    for (int m = 0; m < 2; m++)
#pragma unroll
                        for (int p = 0; p < 4; p++)
#pragma unroll
                            for (int h = 0; h < 2; h++)
                                hmma(acc[m][p * 2 + h], ahi[m], &blo[p][h * 2]);
                }
            }
        } else {
#pragma unroll
            for (int ks = 0; ks < 2; ks++) {
                const int k0 = ks * 16;
                uint32_t ahi[2][4], bhi[4][4];
#pragma unroll
                for (int m = 0; m < 2; m++)
                    ldsm4(ahi[m], st + S3_AHI + (uint32_t)((wm * 32 + m * 16 + (lane & 15)) * APAD
                                                           + k0 + (lane >> 4) * 8) * 2);
#pragma unroll
                for (int p = 0; p < 4; p++)
                    ldsm4t(bhi[p], st + S3_BHI + (uint32_t)((k0 + (lane & 15)) * BPAD
                                                            + wn * 64 + p * 16 + (lane >> 4) * 8) * 2);
#pragma unroll
                for (int m = 0; m < 2; m++)
#pragma unroll
                    for (int p = 0; p < 4; p++)
#pragma unroll
                        for (int h = 0; h < 2; h++)
                            hmma(acc[m][p * 2 + h], ahi[m], &bhi[p][h * 2]);
            }
        }
        __syncthreads();
    }

    // write-only epilogue: leaky_relu, single store
    const int row0 = mb + wm * 32 + (lane >> 2);
    const int col0 = nb + wn * 64 + (lane & 3) * 2;
#pragma unroll
    for (int m = 0; m < 2; m++)
#pragma unroll
        for (int ns = 0; ns < 8; ns++) {
            float h0 = acc[m][ns][0], h1 = acc[m][ns][1];
            float h2 = acc[m][ns][2], h3 = acc[m][ns][3];
            h0 = (h0 > 0.f) ? h0 : 0.01f * h0;
            h1 = (h1 > 0.f) ? h1 : 0.01f * h1;
            h2 = (h2 > 0.f) ? h2 : 0.01f * h2;
            h3 = (h3 > 0.f) ? h3 : 0.01f * h3;
            float* c0 = out + (size_t)(row0 + m * 16) * NDIM + col0 + ns * 8;
            float* c1 = c0 + 8 * NDIM;
            *(float2*)c0 = make_float2(h0, h1);
            *(float2*)c1 = make_float2(h2, h3);
        }
}

// ---------------------------------------------------------------------------
extern "C" void kernel_launch(void* const* d_in, const int* in_sizes, int n_in,
                              void* d_out, int out_size)
{
    const float* X    = (const float*)d_in[0];
    const float* adj  = (const float*)d_in[1];
    const float* W_l  = (const float*)d_in[2];
    const float* W_l1 = (const float*)d_in[3];
    float* out = (float*)d_out;

    cudaFuncSetAttribute(aggx_kernel,    cudaFuncAttributeMaxDynamicSharedMemorySize, SMEM1T);
    cudaFuncSetAttribute(biggemm_kernel, cudaFuncAttributeMaxDynamicSharedMemorySize, SMEM3);

    adjprep_kernel<<<MTOT, 192>>>(adj);
    splitx_kernel<<<(MTOT * NDIM) / 1024, 256>>>(X);
    splitw_kernel<<<(NDIM * NDIM) / 1024, 256>>>(W_l, W_l1);

    aggx_kernel<<<dim3(6, 6, 32), 256, SMEM1T>>>();
    biggemm_kernel<<<dim3(6, 192), 256, SMEM3>>>(out);
}